// round 1
// baseline (speedup 1.0000x reference)
#include <cuda_runtime.h>
#include <cuda_bf16.h>
#include <cstdint>

#define NUSERS 100000
#define NJOBS  100000
#define NN     200000
#define EE     3200000
#define DD     64
#define BB     16384

// ---------------- scratch (static device globals; no allocation) ----------------
__device__ float g_h[(size_t)NN * DD];     // GEMM output per layer
__device__ float g_agg[(size_t)NN * DD];   // aggregation output per layer
__device__ float g_deg[NN];
__device__ float g_dinv[NN];
__device__ int   g_is64_e, g_is64_u, g_is64_j;

// ---------------- dtype detection (int32 vs int64 index buffers) ----------------
// Values are < 200000 and non-negative. If the buffer is int64, every odd int32
// word is 0. If int32, odd words are random node ids (P(zero) ~ 5e-6 each).
__global__ void k_detect(const int* e32, const int* u32, const int* j32) {
    __shared__ int any_e, any_u, any_j;
    if (threadIdx.x == 0) { any_e = any_u = any_j = 0; }
    __syncthreads();
    for (int i = threadIdx.x; i < 2048; i += blockDim.x) {
        if (e32[2 * i + 1]) atomicOr(&any_e, 1);
        if (u32[2 * i + 1]) atomicOr(&any_u, 1);
        if (j32[2 * i + 1]) atomicOr(&any_j, 1);
    }
    __syncthreads();
    if (threadIdx.x == 0) {
        g_is64_e = !any_e;
        g_is64_u = !any_u;
        g_is64_j = !any_j;
    }
}

__device__ __forceinline__ int fetch_idx(const void* p, long long i, int is64) {
    return is64 ? (int)((const long long*)p)[i] : ((const int*)p)[i];
}

// ---------------- degree / norm ----------------
__global__ void k_deg_init() {
    int i = blockIdx.x * blockDim.x + threadIdx.x;
    if (i < NN) g_deg[i] = 1.0f;   // self-loop
}

__global__ void k_deg_count(const void* edges) {
    int is64 = g_is64_e;
    long long stride = (long long)gridDim.x * blockDim.x;
    for (long long e = blockIdx.x * (long long)blockDim.x + threadIdx.x; e < EE; e += stride) {
        int c = fetch_idx(edges, EE + e, is64);  // col = edge_index[1]
        atomicAdd(&g_deg[c], 1.0f);
    }
}

__global__ void k_dinv() {
    int i = blockIdx.x * blockDim.x + threadIdx.x;
    if (i < NN) g_dinv[i] = rsqrtf(g_deg[i]);
}

// ---------------- GEMM: out[node] = act(in[node] (+bias, relu)) @ W ----------------
// 256 threads per block, 64 rows per block. W is 64x64 row-major.
// srcB != nullptr  => layer-1 mode: rows come from concat(userEmb, jobEmb).
// bias != nullptr  => apply (v + bias) then (do_relu ? relu : id) to INPUT rows.
__global__ void k_gemm(const float* __restrict__ srcA, const float* __restrict__ srcB,
                       const float* __restrict__ bias, int do_relu,
                       const float* __restrict__ W, float* __restrict__ out) {
    __shared__ float xs[64][65];
    __shared__ float ws[64 * 64];

    int tid  = threadIdx.x;
    int row0 = blockIdx.x * 64;

    // load W (4096 floats) as float4
    for (int idx = tid; idx < 1024; idx += 256)
        ((float4*)ws)[idx] = ((const float4*)W)[idx];

    // load 64 input rows into xs (with optional bias+relu)
    for (int t = tid; t < 64 * 16; t += 256) {
        int r = t >> 4, q = t & 15;
        int node = row0 + r;
        const float* src;
        if (srcB) {
            src = (node < NUSERS) ? (srcA + (size_t)node * DD)
                                  : (srcB + (size_t)(node - NUSERS) * DD);
        } else {
            src = srcA + (size_t)node * DD;
        }
        float4 v = ((const float4*)src)[q];
        if (bias) {
            v.x += bias[q * 4 + 0]; v.y += bias[q * 4 + 1];
            v.z += bias[q * 4 + 2]; v.w += bias[q * 4 + 3];
        }
        if (do_relu) {
            v.x = fmaxf(v.x, 0.f); v.y = fmaxf(v.y, 0.f);
            v.z = fmaxf(v.z, 0.f); v.w = fmaxf(v.w, 0.f);
        }
        xs[r][q * 4 + 0] = v.x; xs[r][q * 4 + 1] = v.y;
        xs[r][q * 4 + 2] = v.z; xs[r][q * 4 + 3] = v.w;
    }
    __syncthreads();

    // each thread: row r = tid>>2, column groups g*4 + j*16 (g = tid&3, j=0..3)
    int r = tid >> 2;
    int g = tid & 3;
    float4 a0 = {0,0,0,0}, a1 = {0,0,0,0}, a2 = {0,0,0,0}, a3 = {0,0,0,0};

#pragma unroll 8
    for (int k = 0; k < 64; ++k) {
        float xv = xs[r][k];
        const float4* wr = ((const float4*)(ws + k * 64)) + g;
        float4 w0 = wr[0], w1 = wr[4], w2 = wr[8], w3 = wr[12];
        a0.x += xv * w0.x; a0.y += xv * w0.y; a0.z += xv * w0.z; a0.w += xv * w0.w;
        a1.x += xv * w1.x; a1.y += xv * w1.y; a1.z += xv * w1.z; a1.w += xv * w1.w;
        a2.x += xv * w2.x; a2.y += xv * w2.y; a2.z += xv * w2.z; a2.w += xv * w2.w;
        a3.x += xv * w3.x; a3.y += xv * w3.y; a3.z += xv * w3.z; a3.w += xv * w3.w;
    }

    int node = row0 + r;
    float4* o = (float4*)(out + (size_t)node * DD);
    o[g]      = a0;
    o[g + 4]  = a1;
    o[g + 8]  = a2;
    o[g + 12] = a3;
}

// ---------------- self-loop init: agg = h * dinv^2 ----------------
__global__ void k_selfinit(const float* __restrict__ h, float* __restrict__ agg) {
    long long idx = blockIdx.x * (long long)blockDim.x + threadIdx.x;  // one float4 each
    if (idx >= (long long)NN * 16) return;
    int node = (int)(idx >> 4);
    float s = g_dinv[node];
    s *= s;
    float4 v = ((const float4*)h)[idx];
    v.x *= s; v.y *= s; v.z *= s; v.w *= s;
    ((float4*)agg)[idx] = v;
}

// ---------------- edge scatter: agg[col] += h[row] * dinv[row]*dinv[col] ----------------
// Half-warp (16 lanes) per edge -> one red.add.v4.f32 per lane.
__device__ __forceinline__ void red_add_f4(float4* p, float4 v) {
    asm volatile("red.global.add.v4.f32 [%0], {%1, %2, %3, %4};"
                 :: "l"(p), "f"(v.x), "f"(v.y), "f"(v.z), "f"(v.w) : "memory");
}

__global__ void k_scatter(const void* edges, const float* __restrict__ h,
                          float* __restrict__ agg) {
    int is64 = g_is64_e;
    int lane = threadIdx.x & 31;
    int sub  = lane >> 4;           // which of the 2 edges in this warp
    int q    = lane & 15;           // float4 slot within the row
    long long wid   = (blockIdx.x * (long long)blockDim.x + threadIdx.x) >> 5;
    long long nwarp = (gridDim.x * (long long)blockDim.x) >> 5;

    for (long long base = wid * 2; base < EE; base += nwarp * 2) {
        long long e = base + sub;
        if (e >= EE) continue;
        int r = fetch_idx(edges, e, is64);
        int c = fetch_idx(edges, EE + e, is64);
        float nrm = g_dinv[r] * g_dinv[c];
        float4 v = ((const float4*)h)[(size_t)r * 16 + q];
        v.x *= nrm; v.y *= nrm; v.z *= nrm; v.w *= nrm;
        red_add_f4(((float4*)agg) + (size_t)c * 16 + q, v);
    }
}

// ---------------- predictor ----------------
__global__ void k_predict(const void* uidx, const void* jidx,
                          const float* __restrict__ x,   // g_agg (layer-2, pre-bias)
                          const float* __restrict__ b2,
                          const float* __restrict__ pw,  // [128]
                          const float* __restrict__ pb,  // [1]
                          float* __restrict__ out) {
    int lane = threadIdx.x & 31;
    int b = (blockIdx.x * blockDim.x + threadIdx.x) >> 5;
    if (b >= BB) return;
    int u = fetch_idx(uidx, b, g_is64_u);
    int j = fetch_idx(jidx, b, g_is64_j);
    const float* xu = x + (size_t)u * DD;
    const float* xj = x + (size_t)(NUSERS + j) * DD;

    int d0 = lane, d1 = lane + 32;
    float s = (xu[d0] + b2[d0]) * pw[d0]
            + (xu[d1] + b2[d1]) * pw[d1]
            + (xj[d0] + b2[d0]) * pw[DD + d0]
            + (xj[d1] + b2[d1]) * pw[DD + d1];
#pragma unroll
    for (int o = 16; o > 0; o >>= 1) s += __shfl_down_sync(0xFFFFFFFFu, s, o);
    if (lane == 0) out[b] = s + pb[0];
}

// ---------------- launch ----------------
extern "C" void kernel_launch(void* const* d_in, const int* in_sizes, int n_in,
                              void* d_out, int out_size) {
    const void*  edges    = d_in[0];
    const void*  uidx     = d_in[1];
    const void*  jidx     = d_in[2];
    const float* user_emb = (const float*)d_in[3];
    const float* job_emb  = (const float*)d_in[4];
    const float* W1 = (const float*)d_in[5];
    const float* b1 = (const float*)d_in[6];
    const float* W2 = (const float*)d_in[7];
    const float* b2 = (const float*)d_in[8];
    const float* pw = (const float*)d_in[9];
    const float* pb = (const float*)d_in[10];
    float* out = (float*)d_out;

    float *gh, *gagg;
    cudaGetSymbolAddress((void**)&gh, g_h);
    cudaGetSymbolAddress((void**)&gagg, g_agg);

    k_detect<<<1, 256>>>((const int*)edges, (const int*)uidx, (const int*)jidx);

    k_deg_init<<<(NN + 255) / 256, 256>>>();
    k_deg_count<<<2048, 256>>>(edges);
    k_dinv<<<(NN + 255) / 256, 256>>>();

    // ---- layer 1 ----
    k_gemm<<<NN / 64, 256>>>(user_emb, job_emb, nullptr, 0, W1, gh);
    k_selfinit<<<(NN * 16 + 255) / 256, 256>>>(gh, gagg);
    k_scatter<<<4096, 256>>>(edges, gh, gagg);

    // ---- layer 2 (input = relu(agg + b1)) ----
    k_gemm<<<NN / 64, 256>>>(gagg, nullptr, b1, 1, W2, gh);
    k_selfinit<<<(NN * 16 + 255) / 256, 256>>>(gh, gagg);
    k_scatter<<<4096, 256>>>(edges, gh, gagg);

    // ---- predictor (adds b2 inline) ----
    k_predict<<<(BB * 32 + 255) / 256, 256>>>(uidx, jidx, gagg, b2, pw, pb, out);
}

// round 3
// speedup vs baseline: 1.4360x; 1.4360x over previous
#include <cuda_runtime.h>
#include <cuda_bf16.h>
#include <cstdint>

#define NUSERS 100000
#define NJOBS  100000
#define NN     200000
#define EE     3200000
#define DD     64
#define BB     16384
#define NBLK_SCAN 196   // ceil(NN/1024)

// ---------------- scratch (static device globals; no allocation) ----------------
__device__ float g_h[(size_t)NN * DD];     // h' = (x@W) * dinv[row]
__device__ float g_agg[(size_t)NN * DD];   // aggregation output per layer
__device__ int   g_cnt[NN];                // in-degree counts (no self-loop)
__device__ float g_dinv[NN];
__device__ int   g_off[NN + 1];            // CSR offsets (by col)
__device__ int   g_cursor[NN];             // fill cursors
__device__ int   g_csr[EE];                // source node per CSR slot
__device__ int   g_bsum[NBLK_SCAN];        // scan block sums
__device__ int   g_bpre[NBLK_SCAN];        // scan block prefixes
__device__ int   g_is64_e, g_is64_u, g_is64_j;

// ---------------- dtype detection (int32 vs int64 index buffers) ----------------
__global__ void k_detect(const int* e32, const int* u32, const int* j32) {
    __shared__ int any_e, any_u, any_j;
    if (threadIdx.x == 0) { any_e = any_u = any_j = 0; }
    __syncthreads();
    for (int i = threadIdx.x; i < 2048; i += blockDim.x) {
        if (e32[2 * i + 1]) atomicOr(&any_e, 1);
        if (u32[2 * i + 1]) atomicOr(&any_u, 1);
        if (j32[2 * i + 1]) atomicOr(&any_j, 1);
    }
    __syncthreads();
    if (threadIdx.x == 0) {
        g_is64_e = !any_e;
        g_is64_u = !any_u;
        g_is64_j = !any_j;
    }
}

__device__ __forceinline__ int fetch_idx(const void* p, long long i, int is64) {
    return is64 ? (int)((const long long*)p)[i] : ((const int*)p)[i];
}

// ---------------- CSR build ----------------
__global__ void k_zero() {
    int i = blockIdx.x * blockDim.x + threadIdx.x;
    if (i < NN) g_cnt[i] = 0;
}

__global__ void k_count(const void* edges) {
    int e = blockIdx.x * blockDim.x + threadIdx.x;   // 12500*256 == EE exactly
    int c = fetch_idx(edges, (long long)EE + e, g_is64_e);
    atomicAdd(&g_cnt[c], 1);
}

__global__ void k_dinv() {
    int i = blockIdx.x * blockDim.x + threadIdx.x;
    if (i < NN) g_dinv[i] = rsqrtf((float)(g_cnt[i] + 1));  // +1 = self-loop
}

// block-level exclusive scan of g_cnt (1024 elems / block)
__global__ void k_scanA() {
    __shared__ int sh[1024];
    int t = threadIdx.x;
    int i = blockIdx.x * 1024 + t;
    int v = (i < NN) ? g_cnt[i] : 0;
    sh[t] = v;
    __syncthreads();
    for (int o = 1; o < 1024; o <<= 1) {
        int add = (t >= o) ? sh[t - o] : 0;
        __syncthreads();
        sh[t] += add;
        __syncthreads();
    }
    if (i < NN) g_off[i] = sh[t] - v;          // exclusive within block
    if (t == 1023) g_bsum[blockIdx.x] = sh[t]; // block total
}

__global__ void k_scanB() {
    __shared__ int sh[256];
    int t = threadIdx.x;
    int v = (t < NBLK_SCAN) ? g_bsum[t] : 0;
    sh[t] = v;
    __syncthreads();
    for (int o = 1; o < 256; o <<= 1) {
        int add = (t >= o) ? sh[t - o] : 0;
        __syncthreads();
        sh[t] += add;
        __syncthreads();
    }
    if (t < NBLK_SCAN) g_bpre[t] = sh[t] - v;  // exclusive block prefix
    if (t == 0) g_off[NN] = EE;
}

__global__ void k_scanC() {
    int i = blockIdx.x * blockDim.x + threadIdx.x;
    if (i < NN) {
        int o = g_off[i] + g_bpre[i >> 10];
        g_off[i] = o;
        g_cursor[i] = o;
    }
}

__global__ void k_fill(const void* edges) {
    int e = blockIdx.x * blockDim.x + threadIdx.x;
    int is64 = g_is64_e;
    int r = fetch_idx(edges, e, is64);
    int c = fetch_idx(edges, (long long)EE + e, is64);
    int pos = atomicAdd(&g_cursor[c], 1);
    g_csr[pos] = r;
}

// ---------------- GEMM: out[node] = act(in[node] (+bias, relu)) @ W * dinv[node] ----------------
__global__ void k_gemm(const float* __restrict__ srcA, const float* __restrict__ srcB,
                       const float* __restrict__ bias, int do_relu,
                       const float* __restrict__ W, float* __restrict__ out) {
    __shared__ float xs[64][65];
    __shared__ float ws[64 * 64];

    int tid  = threadIdx.x;
    int row0 = blockIdx.x * 64;

    for (int idx = tid; idx < 1024; idx += 256)
        ((float4*)ws)[idx] = ((const float4*)W)[idx];

    for (int t = tid; t < 64 * 16; t += 256) {
        int r = t >> 4, q = t & 15;
        int node = row0 + r;
        const float* src;
        if (srcB) {
            src = (node < NUSERS) ? (srcA + (size_t)node * DD)
                                  : (srcB + (size_t)(node - NUSERS) * DD);
        } else {
            src = srcA + (size_t)node * DD;
        }
        float4 v = ((const float4*)src)[q];
        if (bias) {
            v.x += bias[q * 4 + 0]; v.y += bias[q * 4 + 1];
            v.z += bias[q * 4 + 2]; v.w += bias[q * 4 + 3];
        }
        if (do_relu) {
            v.x = fmaxf(v.x, 0.f); v.y = fmaxf(v.y, 0.f);
            v.z = fmaxf(v.z, 0.f); v.w = fmaxf(v.w, 0.f);
        }
        xs[r][q * 4 + 0] = v.x; xs[r][q * 4 + 1] = v.y;
        xs[r][q * 4 + 2] = v.z; xs[r][q * 4 + 3] = v.w;
    }
    __syncthreads();

    int r = tid >> 2;
    int g = tid & 3;
    float4 a0 = {0,0,0,0}, a1 = {0,0,0,0}, a2 = {0,0,0,0}, a3 = {0,0,0,0};

#pragma unroll 8
    for (int k = 0; k < 64; ++k) {
        float xv = xs[r][k];
        const float4* wr = ((const float4*)(ws + k * 64)) + g;
        float4 w0 = wr[0], w1 = wr[4], w2 = wr[8], w3 = wr[12];
        a0.x += xv * w0.x; a0.y += xv * w0.y; a0.z += xv * w0.z; a0.w += xv * w0.w;
        a1.x += xv * w1.x; a1.y += xv * w1.y; a1.z += xv * w1.z; a1.w += xv * w1.w;
        a2.x += xv * w2.x; a2.y += xv * w2.y; a2.z += xv * w2.z; a2.w += xv * w2.w;
        a3.x += xv * w3.x; a3.y += xv * w3.y; a3.z += xv * w3.z; a3.w += xv * w3.w;
    }

    int node = row0 + r;
    float s = g_dinv[node];   // fuse h' = h * dinv[row]
    a0.x *= s; a0.y *= s; a0.z *= s; a0.w *= s;
    a1.x *= s; a1.y *= s; a1.z *= s; a1.w *= s;
    a2.x *= s; a2.y *= s; a2.z *= s; a2.w *= s;
    a3.x *= s; a3.y *= s; a3.z *= s; a3.w *= s;

    float4* o = (float4*)(out + (size_t)node * DD);
    o[g]      = a0;
    o[g + 4]  = a1;
    o[g + 8]  = a2;
    o[g + 12] = a3;
}

// ---------------- gather: agg[n] = dinv[n] * (h'[n] + sum_{in-edges} h'[src]) ----------------
// warp per node; half-warp per edge; q = float4 slot (16 per row)
__global__ void k_gather(const float* __restrict__ hp, float* __restrict__ agg) {
    int tid  = blockIdx.x * blockDim.x + threadIdx.x;
    int n    = tid >> 5;
    if (n >= NN) return;
    int lane = threadIdx.x & 31;
    int q    = lane & 15;
    int half = lane >> 4;

    int beg = g_off[n];
    int end = g_off[n + 1];

    // self term (loaded early for latency overlap; used on half 0 only)
    float4 self = ((const float4*)hp)[(size_t)n * 16 + q];

    float4 a0 = {0,0,0,0}, a1 = {0,0,0,0};
    int e = beg + half;
    // 2-deep unroll for MLP
    while (e + 2 < end) {
        int s0 = g_csr[e];
        int s1 = g_csr[e + 2];
        float4 v0 = ((const float4*)hp)[(size_t)s0 * 16 + q];
        float4 v1 = ((const float4*)hp)[(size_t)s1 * 16 + q];
        a0.x += v0.x; a0.y += v0.y; a0.z += v0.z; a0.w += v0.w;
        a1.x += v1.x; a1.y += v1.y; a1.z += v1.z; a1.w += v1.w;
        e += 4;
    }
    if (e < end) {
        int s0 = g_csr[e];
        float4 v0 = ((const float4*)hp)[(size_t)s0 * 16 + q];
        a0.x += v0.x; a0.y += v0.y; a0.z += v0.z; a0.w += v0.w;
    }
    a0.x += a1.x; a0.y += a1.y; a0.z += a1.z; a0.w += a1.w;

    // merge the two half-warps
    a0.x += __shfl_xor_sync(0xFFFFFFFFu, a0.x, 16);
    a0.y += __shfl_xor_sync(0xFFFFFFFFu, a0.y, 16);
    a0.z += __shfl_xor_sync(0xFFFFFFFFu, a0.z, 16);
    a0.w += __shfl_xor_sync(0xFFFFFFFFu, a0.w, 16);

    if (half == 0) {
        float s = g_dinv[n];
        float4 r;
        r.x = (a0.x + self.x) * s;
        r.y = (a0.y + self.y) * s;
        r.z = (a0.z + self.z) * s;
        r.w = (a0.w + self.w) * s;
        ((float4*)agg)[(size_t)n * 16 + q] = r;
    }
}

// ---------------- predictor ----------------
__global__ void k_predict(const void* uidx, const void* jidx,
                          const float* __restrict__ x,
                          const float* __restrict__ b2,
                          const float* __restrict__ pw,
                          const float* __restrict__ pb,
                          float* __restrict__ out) {
    int lane = threadIdx.x & 31;
    int b = (blockIdx.x * blockDim.x + threadIdx.x) >> 5;
    if (b >= BB) return;
    int u = fetch_idx(uidx, b, g_is64_u);
    int j = fetch_idx(jidx, b, g_is64_j);
    const float* xu = x + (size_t)u * DD;
    const float* xj = x + (size_t)(NUSERS + j) * DD;

    int d0 = lane, d1 = lane + 32;
    float s = (xu[d0] + b2[d0]) * pw[d0]
            + (xu[d1] + b2[d1]) * pw[d1]
            + (xj[d0] + b2[d0]) * pw[DD + d0]
            + (xj[d1] + b2[d1]) * pw[DD + d1];
#pragma unroll
    for (int o = 16; o > 0; o >>= 1) s += __shfl_down_sync(0xFFFFFFFFu, s, o);
    if (lane == 0) out[b] = s + pb[0];
}

// ---------------- launch ----------------
extern "C" void kernel_launch(void* const* d_in, const int* in_sizes, int n_in,
                              void* d_out, int out_size) {
    const void*  edges    = d_in[0];
    const void*  uidx     = d_in[1];
    const void*  jidx     = d_in[2];
    const float* user_emb = (const float*)d_in[3];
    const float* job_emb  = (const float*)d_in[4];
    const float* W1 = (const float*)d_in[5];
    const float* b1 = (const float*)d_in[6];
    const float* W2 = (const float*)d_in[7];
    const float* b2 = (const float*)d_in[8];
    const float* pw = (const float*)d_in[9];
    const float* pb = (const float*)d_in[10];
    float* out = (float*)d_out;

    float *gh, *gagg;
    cudaGetSymbolAddress((void**)&gh, g_h);
    cudaGetSymbolAddress((void**)&gagg, g_agg);

    k_detect<<<1, 256>>>((const int*)edges, (const int*)uidx, (const int*)jidx);

    // CSR build (amortized over both layers)
    k_zero<<<(NN + 255) / 256, 256>>>();
    k_count<<<EE / 256, 256>>>(edges);
    k_dinv<<<(NN + 255) / 256, 256>>>();
    k_scanA<<<NBLK_SCAN, 1024>>>();
    k_scanB<<<1, 256>>>();
    k_scanC<<<(NN + 255) / 256, 256>>>();
    k_fill<<<EE / 256, 256>>>(edges);

    // ---- layer 1 ----
    k_gemm<<<NN / 64, 256>>>(user_emb, job_emb, nullptr, 0, W1, gh);
    k_gather<<<(NN * 32 + 255) / 256, 256>>>(gh, gagg);

    // ---- layer 2 ----
    k_gemm<<<NN / 64, 256>>>(gagg, nullptr, b1, 1, W2, gh);
    k_gather<<<(NN * 32 + 255) / 256, 256>>>(gh, gagg);

    // ---- predictor ----
    k_predict<<<(BB * 32 + 255) / 256, 256>>>(uidx, jidx, gagg, b2, pw, pb, out);
}

// round 4
// speedup vs baseline: 1.5464x; 1.0769x over previous
#include <cuda_runtime.h>
#include <cuda_fp16.h>
#include <cstdint>

#define NUSERS 100000
#define NJOBS  100000
#define NN     200000
#define EE     3200000
#define DD     64
#define BB     16384
#define NBLK_SCAN 196   // ceil(NN/1024)

// ---------------- scratch (static device globals; no allocation) ----------------
__device__ __half g_h16[(size_t)NN * DD];  // h' = (x@W) * dinv[row], fp16 (25.6MB)
__device__ float  g_agg[(size_t)NN * DD];  // aggregation output per layer (fp32)
__device__ int    g_cnt[NN];               // in-degree counts (no self-loop)
__device__ float  g_dinv[NN];
__device__ int    g_off[NN + 1];           // CSR offsets (by col)
__device__ int    g_cursor[NN];            // fill cursors
__device__ int    g_csr[EE];               // source node per CSR slot
__device__ int    g_bsum[NBLK_SCAN];
__device__ int    g_bpre[NBLK_SCAN];
__device__ int    g_is64_e, g_is64_u, g_is64_j;

// ---------------- detect (block 0) + zero counts (whole grid) ----------------
__global__ void k_detect_zero(const int* e32, const int* u32, const int* j32) {
    int i = blockIdx.x * blockDim.x + threadIdx.x;
    if (i < NN) g_cnt[i] = 0;
    if (blockIdx.x == 0) {
        __shared__ int any_e, any_u, any_j;
        if (threadIdx.x == 0) { any_e = any_u = any_j = 0; }
        __syncthreads();
        for (int k = threadIdx.x; k < 2048; k += blockDim.x) {
            if (e32[2 * k + 1]) atomicOr(&any_e, 1);
            if (u32[2 * k + 1]) atomicOr(&any_u, 1);
            if (j32[2 * k + 1]) atomicOr(&any_j, 1);
        }
        __syncthreads();
        if (threadIdx.x == 0) {
            g_is64_e = !any_e;
            g_is64_u = !any_u;
            g_is64_j = !any_j;
        }
    }
}

__device__ __forceinline__ int fetch_idx(const void* p, long long i, int is64) {
    return is64 ? (int)((const long long*)p)[i] : ((const int*)p)[i];
}

// ---------------- CSR build ----------------
__global__ void k_count(const void* edges) {
    int e = blockIdx.x * blockDim.x + threadIdx.x;   // EE == 12500*256 exactly
    int c = fetch_idx(edges, (long long)EE + e, g_is64_e);
    atomicAdd(&g_cnt[c], 1);
}

// warp-shuffle exclusive scan, 1024 elems / block
__global__ void k_scanA() {
    __shared__ int wsum[32];
    int t = threadIdx.x;
    int i = blockIdx.x * 1024 + t;
    int v = (i < NN) ? g_cnt[i] : 0;
    int x = v;
#pragma unroll
    for (int o = 1; o < 32; o <<= 1) {
        int y = __shfl_up_sync(0xFFFFFFFFu, x, o);
        if ((t & 31) >= o) x += y;
    }
    if ((t & 31) == 31) wsum[t >> 5] = x;
    __syncthreads();
    if (t < 32) {
        int s = wsum[t];
#pragma unroll
        for (int o = 1; o < 32; o <<= 1) {
            int y = __shfl_up_sync(0xFFFFFFFFu, s, o);
            if (t >= o) s += y;
        }
        wsum[t] = s;
    }
    __syncthreads();
    int pre = (t >= 32) ? wsum[(t >> 5) - 1] : 0;
    int incl = x + pre;
    if (i < NN) g_off[i] = incl - v;          // exclusive within block
    if (t == 1023) g_bsum[blockIdx.x] = incl; // block total
}

__global__ void k_scanB() {
    __shared__ int wsum[8];
    int t = threadIdx.x;  // 256 threads
    int v = (t < NBLK_SCAN) ? g_bsum[t] : 0;
    int x = v;
#pragma unroll
    for (int o = 1; o < 32; o <<= 1) {
        int y = __shfl_up_sync(0xFFFFFFFFu, x, o);
        if ((t & 31) >= o) x += y;
    }
    if ((t & 31) == 31) wsum[t >> 5] = x;
    __syncthreads();
    if (t == 0) {
        int s = 0;
#pragma unroll
        for (int k = 0; k < 8; k++) { int tmp = wsum[k]; wsum[k] = s; s += tmp; }
    }
    __syncthreads();
    int pre = wsum[t >> 5];
    if (t < NBLK_SCAN) g_bpre[t] = x + pre - v;  // exclusive block prefix
    if (t == 0) g_off[NN] = EE;
}

// finalize offsets + cursors + dinv (fused)
__global__ void k_scanC() {
    int i = blockIdx.x * blockDim.x + threadIdx.x;
    if (i < NN) {
        int o = g_off[i] + g_bpre[i >> 10];
        g_off[i] = o;
        g_cursor[i] = o;
        g_dinv[i] = rsqrtf((float)(g_cnt[i] + 1));  // +1 = self-loop
    }
}

__global__ void k_fill(const void* edges) {
    int e = blockIdx.x * blockDim.x + threadIdx.x;
    int is64 = g_is64_e;
    int r = fetch_idx(edges, e, is64);
    int c = fetch_idx(edges, (long long)EE + e, is64);
    int pos = atomicAdd(&g_cursor[c], 1);
    g_csr[pos] = r;
}

// ---------------- GEMM: h16[node] = (act(in[node]) @ W) * dinv[node], fp16 out ----------------
__device__ __forceinline__ uint2 pack4h(float4 a, float s) {
    __half2 lo = __floats2half2_rn(a.x * s, a.y * s);
    __half2 hi = __floats2half2_rn(a.z * s, a.w * s);
    uint2 u;
    u.x = *(unsigned*)&lo;
    u.y = *(unsigned*)&hi;
    return u;
}

__global__ void k_gemm(const float* __restrict__ srcA, const float* __restrict__ srcB,
                       const float* __restrict__ bias, int do_relu,
                       const float* __restrict__ W, __half* __restrict__ out) {
    __shared__ float xs[64][65];
    __shared__ float ws[64 * 64];

    int tid  = threadIdx.x;
    int row0 = blockIdx.x * 64;

    for (int idx = tid; idx < 1024; idx += 256)
        ((float4*)ws)[idx] = ((const float4*)W)[idx];

    for (int t = tid; t < 64 * 16; t += 256) {
        int r = t >> 4, q = t & 15;
        int node = row0 + r;
        const float* src;
        if (srcB) {
            src = (node < NUSERS) ? (srcA + (size_t)node * DD)
                                  : (srcB + (size_t)(node - NUSERS) * DD);
        } else {
            src = srcA + (size_t)node * DD;
        }
        float4 v = ((const float4*)src)[q];
        if (bias) {
            v.x += bias[q * 4 + 0]; v.y += bias[q * 4 + 1];
            v.z += bias[q * 4 + 2]; v.w += bias[q * 4 + 3];
        }
        if (do_relu) {
            v.x = fmaxf(v.x, 0.f); v.y = fmaxf(v.y, 0.f);
            v.z = fmaxf(v.z, 0.f); v.w = fmaxf(v.w, 0.f);
        }
        xs[r][q * 4 + 0] = v.x; xs[r][q * 4 + 1] = v.y;
        xs[r][q * 4 + 2] = v.z; xs[r][q * 4 + 3] = v.w;
    }
    __syncthreads();

    int r = tid >> 2;
    int g = tid & 3;
    float4 a0 = {0,0,0,0}, a1 = {0,0,0,0}, a2 = {0,0,0,0}, a3 = {0,0,0,0};

#pragma unroll 8
    for (int k = 0; k < 64; ++k) {
        float xv = xs[r][k];
        const float4* wr = ((const float4*)(ws + k * 64)) + g;
        float4 w0 = wr[0], w1 = wr[4], w2 = wr[8], w3 = wr[12];
        a0.x += xv * w0.x; a0.y += xv * w0.y; a0.z += xv * w0.z; a0.w += xv * w0.w;
        a1.x += xv * w1.x; a1.y += xv * w1.y; a1.z += xv * w1.z; a1.w += xv * w1.w;
        a2.x += xv * w2.x; a2.y += xv * w2.y; a2.z += xv * w2.z; a2.w += xv * w2.w;
        a3.x += xv * w3.x; a3.y += xv * w3.y; a3.z += xv * w3.z; a3.w += xv * w3.w;
    }

    int node = row0 + r;
    float s = g_dinv[node];
    // half column index g*4 + j*16 -> uint2 (4-half) index g + j*4
    uint2* o = (uint2*)(out + (size_t)node * DD);
    o[g]      = pack4h(a0, s);
    o[g + 4]  = pack4h(a1, s);
    o[g + 8]  = pack4h(a2, s);
    o[g + 12] = pack4h(a3, s);
}

// ---------------- gather: agg[n] = dinv[n] * (h'[n] + sum_{in-edges} h'[src]) ----------------
// warp per node; quarter-warp (8 lanes x 16B) per fp16 row; 4 edges in flight + unroll 2
__device__ __forceinline__ void acc8h(float* f, uint4 v) {
    float2 p0 = __half22float2(*(__half2*)&v.x);
    float2 p1 = __half22float2(*(__half2*)&v.y);
    float2 p2 = __half22float2(*(__half2*)&v.z);
    float2 p3 = __half22float2(*(__half2*)&v.w);
    f[0] += p0.x; f[1] += p0.y; f[2] += p1.x; f[3] += p1.y;
    f[4] += p2.x; f[5] += p2.y; f[6] += p3.x; f[7] += p3.y;
}

__global__ void k_gather(const __half* __restrict__ hp, float* __restrict__ agg) {
    int n = (blockIdx.x * blockDim.x + threadIdx.x) >> 5;
    if (n >= NN) return;
    int lane = threadIdx.x & 31;
    int g = lane >> 3;      // edge group 0..3
    int q = lane & 7;       // uint4 slot within 128B row

    const uint4* h4 = (const uint4*)hp;   // 8 uint4 per row
    int beg = g_off[n];
    int end = g_off[n + 1];

    float f[8] = {0, 0, 0, 0, 0, 0, 0, 0};

    int e = beg + g;
    while (e + 4 < end) {
        int s0 = g_csr[e];
        int s1 = g_csr[e + 4];
        uint4 v0 = h4[(size_t)s0 * 8 + q];
        uint4 v1 = h4[(size_t)s1 * 8 + q];
        acc8h(f, v0);
        acc8h(f, v1);
        e += 8;
    }
    if (e < end) {
        int s0 = g_csr[e];
        acc8h(f, h4[(size_t)s0 * 8 + q]);
    }

    // reduce across the 4 edge groups
#pragma unroll
    for (int i = 0; i < 8; i++) {
        f[i] += __shfl_xor_sync(0xFFFFFFFFu, f[i], 8);
        f[i] += __shfl_xor_sync(0xFFFFFFFFu, f[i], 16);
    }

    if (g == 0) {
        uint4 sv = h4[(size_t)n * 8 + q];   // self term
        float sf[8] = {0, 0, 0, 0, 0, 0, 0, 0};
        acc8h(sf, sv);
        float s = g_dinv[n];
        float4 r0, r1;
        r0.x = (f[0] + sf[0]) * s; r0.y = (f[1] + sf[1]) * s;
        r0.z = (f[2] + sf[2]) * s; r0.w = (f[3] + sf[3]) * s;
        r1.x = (f[4] + sf[4]) * s; r1.y = (f[5] + sf[5]) * s;
        r1.z = (f[6] + sf[6]) * s; r1.w = (f[7] + sf[7]) * s;
        float4* o = (float4*)(agg + (size_t)n * DD + q * 8);
        o[0] = r0;
        o[1] = r1;
    }
}

// ---------------- predictor ----------------
__global__ void k_predict(const void* uidx, const void* jidx,
                          const float* __restrict__ x,
                          const float* __restrict__ b2,
                          const float* __restrict__ pw,
                          const float* __restrict__ pb,
                          float* __restrict__ out) {
    int lane = threadIdx.x & 31;
    int b = (blockIdx.x * blockDim.x + threadIdx.x) >> 5;
    if (b >= BB) return;
    int u = fetch_idx(uidx, b, g_is64_u);
    int j = fetch_idx(jidx, b, g_is64_j);
    const float* xu = x + (size_t)u * DD;
    const float* xj = x + (size_t)(NUSERS + j) * DD;

    int d0 = lane, d1 = lane + 32;
    float s = (xu[d0] + b2[d0]) * pw[d0]
            + (xu[d1] + b2[d1]) * pw[d1]
            + (xj[d0] + b2[d0]) * pw[DD + d0]
            + (xj[d1] + b2[d1]) * pw[DD + d1];
#pragma unroll
    for (int o = 16; o > 0; o >>= 1) s += __shfl_down_sync(0xFFFFFFFFu, s, o);
    if (lane == 0) out[b] = s + pb[0];
}

// ---------------- launch ----------------
extern "C" void kernel_launch(void* const* d_in, const int* in_sizes, int n_in,
                              void* d_out, int out_size) {
    const void*  edges    = d_in[0];
    const void*  uidx     = d_in[1];
    const void*  jidx     = d_in[2];
    const float* user_emb = (const float*)d_in[3];
    const float* job_emb  = (const float*)d_in[4];
    const float* W1 = (const float*)d_in[5];
    const float* b1 = (const float*)d_in[6];
    const float* W2 = (const float*)d_in[7];
    const float* b2 = (const float*)d_in[8];
    const float* pw = (const float*)d_in[9];
    const float* pb = (const float*)d_in[10];
    float* out = (float*)d_out;

    __half* gh;
    float*  gagg;
    cudaGetSymbolAddress((void**)&gh, g_h16);
    cudaGetSymbolAddress((void**)&gagg, g_agg);

    // CSR build (amortized over both layers)
    k_detect_zero<<<(NN + 255) / 256, 256>>>((const int*)edges, (const int*)uidx, (const int*)jidx);
    k_count<<<EE / 256, 256>>>(edges);
    k_scanA<<<NBLK_SCAN, 1024>>>();
    k_scanB<<<1, 256>>>();
    k_scanC<<<(NN + 255) / 256, 256>>>();
    k_fill<<<EE / 256, 256>>>(edges);

    // ---- layer 1 ----
    k_gemm<<<NN / 64, 256>>>(user_emb, job_emb, nullptr, 0, W1, gh);
    k_gather<<<(NN * 32 + 255) / 256, 256>>>(gh, gagg);

    // ---- layer 2 ----
    k_gemm<<<NN / 64, 256>>>(gagg, nullptr, b1, 1, W2, gh);
    k_gather<<<(NN * 32 + 255) / 256, 256>>>(gh, gagg);

    // ---- predictor ----
    k_predict<<<(BB * 32 + 255) / 256, 256>>>(uidx, jidx, gagg, b2, pw, pb, out);
}

// round 5
// speedup vs baseline: 2.4336x; 1.5737x over previous
#include <cuda_runtime.h>
#include <cuda_fp16.h>
#include <cstdint>

#define NUSERS 100000
#define NJOBS  100000
#define NN     200000
#define EE     3200000
#define DD     64
#define BB     16384
#define NBLK_SCAN 196   // ceil(NN/1024)
#define GR 128          // GEMM rows per block

typedef unsigned long long ull;

// ---------------- scratch (static device globals; no allocation) ----------------
__device__ __half g_h16[(size_t)NN * DD];  // h' = (x@W) * dinv[row], fp16
__device__ float  g_agg[(size_t)NN * DD];  // layer-1 aggregation output (fp32)
__device__ int    g_cnt[NN];
__device__ float  g_dinv[NN];
__device__ int    g_off[NN + 1];
__device__ int    g_cursor[NN];
__device__ int    g_csr[EE];
__device__ int    g_bsum[NBLK_SCAN];
__device__ int    g_bpre[NBLK_SCAN];
__device__ int    g_is64_e, g_is64_u, g_is64_j;

// ---------------- f32x2 packed helpers ----------------
__device__ __forceinline__ ull packf2(float lo, float hi) {
    ull r; asm("mov.b64 %0, {%1, %2};" : "=l"(r) : "f"(lo), "f"(hi)); return r;
}
__device__ __forceinline__ void fma2(ull& d, ull a, ull b) {
    asm("fma.rn.f32x2 %0, %1, %2, %0;" : "+l"(d) : "l"(a), "l"(b));
}
__device__ __forceinline__ float2 unpackf2(ull v) {
    float2 r; asm("mov.b64 {%0, %1}, %2;" : "=f"(r.x), "=f"(r.y) : "l"(v)); return r;
}

// ---------------- detect (block 0) + zero counts ----------------
__global__ void k_detect_zero(const int* e32, const int* u32, const int* j32) {
    int i = blockIdx.x * blockDim.x + threadIdx.x;
    if (i < NN) g_cnt[i] = 0;
    if (blockIdx.x == 0) {
        __shared__ int any_e, any_u, any_j;
        if (threadIdx.x == 0) { any_e = any_u = any_j = 0; }
        __syncthreads();
        for (int k = threadIdx.x; k < 2048; k += blockDim.x) {
            if (e32[2 * k + 1]) atomicOr(&any_e, 1);
            if (u32[2 * k + 1]) atomicOr(&any_u, 1);
            if (j32[2 * k + 1]) atomicOr(&any_j, 1);
        }
        __syncthreads();
        if (threadIdx.x == 0) {
            g_is64_e = !any_e;
            g_is64_u = !any_u;
            g_is64_j = !any_j;
        }
    }
}

__device__ __forceinline__ int fetch_idx(const void* p, long long i, int is64) {
    return is64 ? (int)((const long long*)p)[i] : ((const int*)p)[i];
}

// ---------------- CSR build ----------------
__global__ void k_count(const void* edges) {
    int e = blockIdx.x * blockDim.x + threadIdx.x;
    int c = fetch_idx(edges, (long long)EE + e, g_is64_e);
    atomicAdd(&g_cnt[c], 1);
}

__global__ void k_scanA() {
    __shared__ int wsum[32];
    int t = threadIdx.x;
    int i = blockIdx.x * 1024 + t;
    int v = (i < NN) ? g_cnt[i] : 0;
    int x = v;
#pragma unroll
    for (int o = 1; o < 32; o <<= 1) {
        int y = __shfl_up_sync(0xFFFFFFFFu, x, o);
        if ((t & 31) >= o) x += y;
    }
    if ((t & 31) == 31) wsum[t >> 5] = x;
    __syncthreads();
    if (t < 32) {
        int s = wsum[t];
#pragma unroll
        for (int o = 1; o < 32; o <<= 1) {
            int y = __shfl_up_sync(0xFFFFFFFFu, s, o);
            if (t >= o) s += y;
        }
        wsum[t] = s;
    }
    __syncthreads();
    int pre = (t >= 32) ? wsum[(t >> 5) - 1] : 0;
    int incl = x + pre;
    if (i < NN) g_off[i] = incl - v;
    if (t == 1023) g_bsum[blockIdx.x] = incl;
}

__global__ void k_scanB() {
    __shared__ int wsum[8];
    int t = threadIdx.x;
    int v = (t < NBLK_SCAN) ? g_bsum[t] : 0;
    int x = v;
#pragma unroll
    for (int o = 1; o < 32; o <<= 1) {
        int y = __shfl_up_sync(0xFFFFFFFFu, x, o);
        if ((t & 31) >= o) x += y;
    }
    if ((t & 31) == 31) wsum[t >> 5] = x;
    __syncthreads();
    if (t == 0) {
        int s = 0;
#pragma unroll
        for (int k = 0; k < 8; k++) { int tmp = wsum[k]; wsum[k] = s; s += tmp; }
    }
    __syncthreads();
    int pre = wsum[t >> 5];
    if (t < NBLK_SCAN) g_bpre[t] = x + pre - v;
    if (t == 0) g_off[NN] = EE;
}

__global__ void k_scanC() {
    int i = blockIdx.x * blockDim.x + threadIdx.x;
    if (i < NN) {
        int o = g_off[i] + g_bpre[i >> 10];
        g_off[i] = o;
        g_cursor[i] = o;
        g_dinv[i] = rsqrtf((float)(g_cnt[i] + 1));
    }
}

__global__ void k_fill(const void* edges) {
    int e = blockIdx.x * blockDim.x + threadIdx.x;
    int is64 = g_is64_e;
    int r = fetch_idx(edges, e, is64);
    int c = fetch_idx(edges, (long long)EE + e, is64);
    int pos = atomicAdd(&g_cursor[c], 1);
    g_csr[pos] = r;
}

// ---------------- GEMM: h16[node] = (act(in[node]) @ W) * dinv[node], fp16 out ----------------
// 256 threads, GR=128 rows/block. Thread: 8 rows (rg=tid>>4) x 4 cols (cg=tid&15).
// Packed f32x2 FMA on the fma pipe; W pairs come free from LDS.128 (ulonglong2).
__global__ void k_gemm(const float* __restrict__ srcA, const float* __restrict__ srcB,
                       const float* __restrict__ bias, int do_relu,
                       const float* __restrict__ W, __half* __restrict__ out) {
    __shared__ float xs[GR][68];   // padded: 68*4B = 272B row stride (16B aligned)
    __shared__ float ws[64 * 64];

    int tid  = threadIdx.x;
    int row0 = blockIdx.x * GR;

    for (int idx = tid; idx < 1024; idx += 256)
        ((float4*)ws)[idx] = ((const float4*)W)[idx];

    // load GR input rows (coalesced float4), optional bias+relu
    for (int t = tid; t < GR * 16; t += 256) {
        int r = t >> 4, q = t & 15;
        int node = row0 + r;
        int ld = (node < NN) ? node : (NN - 1);
        const float* src;
        if (srcB) {
            src = (ld < NUSERS) ? (srcA + (size_t)ld * DD)
                                : (srcB + (size_t)(ld - NUSERS) * DD);
        } else {
            src = srcA + (size_t)ld * DD;
        }
        float4 v = ((const float4*)src)[q];
        if (bias) {
            v.x += bias[q * 4 + 0]; v.y += bias[q * 4 + 1];
            v.z += bias[q * 4 + 2]; v.w += bias[q * 4 + 3];
        }
        if (do_relu) {
            v.x = fmaxf(v.x, 0.f); v.y = fmaxf(v.y, 0.f);
            v.z = fmaxf(v.z, 0.f); v.w = fmaxf(v.w, 0.f);
        }
        *(float4*)&xs[r][q * 4] = v;
    }
    __syncthreads();

    int rg = tid >> 4;   // 0..15 -> rows rg*8 .. rg*8+7
    int cg = tid & 15;   // 0..15 -> cols cg*4 .. cg*4+3

    ull acc[8][2];
#pragma unroll
    for (int i = 0; i < 8; i++) { acc[i][0] = 0ULL; acc[i][1] = 0ULL; }

#pragma unroll 4
    for (int k4 = 0; k4 < 64; k4 += 4) {
        float4 xr[8];
#pragma unroll
        for (int i = 0; i < 8; i++)
            xr[i] = *(const float4*)&xs[rg * 8 + i][k4];
#pragma unroll
        for (int kk = 0; kk < 4; kk++) {
            ulonglong2 w2 = *(const ulonglong2*)&ws[(k4 + kk) * 64 + cg * 4];
#pragma unroll
            for (int i = 0; i < 8; i++) {
                float xv = (kk == 0) ? xr[i].x : (kk == 1) ? xr[i].y
                         : (kk == 2) ? xr[i].z : xr[i].w;
                ull xx = packf2(xv, xv);
                fma2(acc[i][0], xx, w2.x);
                fma2(acc[i][1], xx, w2.y);
            }
        }
    }

#pragma unroll
    for (int i = 0; i < 8; i++) {
        int node = row0 + rg * 8 + i;
        if (node >= NN) break;
        float s = g_dinv[node];
        float2 p0 = unpackf2(acc[i][0]);
        float2 p1 = unpackf2(acc[i][1]);
        __half2 h0 = __floats2half2_rn(p0.x * s, p0.y * s);
        __half2 h1 = __floats2half2_rn(p1.x * s, p1.y * s);
        uint2 u;
        u.x = *(unsigned*)&h0;
        u.y = *(unsigned*)&h1;
        *(uint2*)(out + (size_t)node * DD + cg * 4) = u;
    }
}

// ---------------- full gather (layer 1): agg[n] = dinv[n]*(h'[n] + sum h'[src]) ----------------
__device__ __forceinline__ void acc8h(float* f, uint4 v) {
    float2 p0 = __half22float2(*(__half2*)&v.x);
    float2 p1 = __half22float2(*(__half2*)&v.y);
    float2 p2 = __half22float2(*(__half2*)&v.z);
    float2 p3 = __half22float2(*(__half2*)&v.w);
    f[0] += p0.x; f[1] += p0.y; f[2] += p1.x; f[3] += p1.y;
    f[4] += p2.x; f[5] += p2.y; f[6] += p3.x; f[7] += p3.y;
}

__global__ void k_gather(const __half* __restrict__ hp, float* __restrict__ agg) {
    int n = (blockIdx.x * blockDim.x + threadIdx.x) >> 5;
    if (n >= NN) return;
    int lane = threadIdx.x & 31;
    int g = lane >> 3;
    int q = lane & 7;

    const uint4* h4 = (const uint4*)hp;
    int beg = g_off[n];
    int end = g_off[n + 1];

    float f[8] = {0, 0, 0, 0, 0, 0, 0, 0};

    int e = beg + g;
    while (e + 4 < end) {
        int s0 = g_csr[e];
        int s1 = g_csr[e + 4];
        uint4 v0 = h4[(size_t)s0 * 8 + q];
        uint4 v1 = h4[(size_t)s1 * 8 + q];
        acc8h(f, v0);
        acc8h(f, v1);
        e += 8;
    }
    if (e < end) {
        acc8h(f, h4[(size_t)g_csr[e] * 8 + q]);
    }

#pragma unroll
    for (int i = 0; i < 8; i++) {
        f[i] += __shfl_xor_sync(0xFFFFFFFFu, f[i], 8);
        f[i] += __shfl_xor_sync(0xFFFFFFFFu, f[i], 16);
    }

    if (g == 0) {
        float sf[8] = {0, 0, 0, 0, 0, 0, 0, 0};
        acc8h(sf, h4[(size_t)n * 8 + q]);
        float s = g_dinv[n];
        float4 r0, r1;
        r0.x = (f[0] + sf[0]) * s; r0.y = (f[1] + sf[1]) * s;
        r0.z = (f[2] + sf[2]) * s; r0.w = (f[3] + sf[3]) * s;
        r1.x = (f[4] + sf[4]) * s; r1.y = (f[5] + sf[5]) * s;
        r1.z = (f[6] + sf[6]) * s; r1.w = (f[7] + sf[7]) * s;
        float4* o = (float4*)(agg + (size_t)n * DD + q * 8);
        o[0] = r0;
        o[1] = r1;
    }
}

// ---------------- fused layer-2 gather + predictor ----------------
// One warp per batch element. side = lane>>4 (0:user, 1:job); sub = (lane>>3)&1
// (edge interleave); q = lane&7 (uint4 slot of the 128B fp16 row).
__global__ void k_gpred(const void* uidx, const void* jidx,
                        const __half* __restrict__ hp,
                        const float* __restrict__ b2,
                        const float* __restrict__ pw,
                        const float* __restrict__ pb,
                        float* __restrict__ out) {
    int b = (blockIdx.x * blockDim.x + threadIdx.x) >> 5;
    if (b >= BB) return;
    int lane = threadIdx.x & 31;
    int side = lane >> 4;
    int sub  = (lane >> 3) & 1;
    int q    = lane & 7;

    int node;
    if (side == 0) node = fetch_idx(uidx, b, g_is64_u);
    else           node = NUSERS + fetch_idx(jidx, b, g_is64_j);

    const uint4* h4 = (const uint4*)hp;
    int beg = g_off[node];
    int end = g_off[node + 1];

    float f[8] = {0, 0, 0, 0, 0, 0, 0, 0};
    int e = beg + sub;
    while (e + 2 < end) {
        int s0 = g_csr[e];
        int s1 = g_csr[e + 2];
        uint4 v0 = h4[(size_t)s0 * 8 + q];
        uint4 v1 = h4[(size_t)s1 * 8 + q];
        acc8h(f, v0);
        acc8h(f, v1);
        e += 4;
    }
    if (e < end) {
        acc8h(f, h4[(size_t)g_csr[e] * 8 + q]);
    }

    // combine the two edge-interleave halves (both end with the full sum)
#pragma unroll
    for (int i = 0; i < 8; i++)
        f[i] += __shfl_xor_sync(0xFFFFFFFFu, f[i], 8);

    // self term + scale + bias + dot with pred_w slice
    acc8h(f, h4[(size_t)node * 8 + q]);
    float s = g_dinv[node];
    int d = q * 8;
    const float* pws = pw + side * DD + d;
    const float* b2s = b2 + d;
    float p = 0.f;
#pragma unroll
    for (int i = 0; i < 8; i++)
        p += (f[i] * s + b2s[i]) * pws[i];

    if (sub) p = 0.f;   // sub=1 duplicates the sum; count once
#pragma unroll
    for (int o = 16; o > 0; o >>= 1)
        p += __shfl_xor_sync(0xFFFFFFFFu, p, o);

    if (lane == 0) out[b] = p + pb[0];
}

// ---------------- launch ----------------
extern "C" void kernel_launch(void* const* d_in, const int* in_sizes, int n_in,
                              void* d_out, int out_size) {
    const void*  edges    = d_in[0];
    const void*  uidx     = d_in[1];
    const void*  jidx     = d_in[2];
    const float* user_emb = (const float*)d_in[3];
    const float* job_emb  = (const float*)d_in[4];
    const float* W1 = (const float*)d_in[5];
    const float* b1 = (const float*)d_in[6];
    const float* W2 = (const float*)d_in[7];
    const float* b2 = (const float*)d_in[8];
    const float* pw = (const float*)d_in[9];
    const float* pb = (const float*)d_in[10];
    float* out = (float*)d_out;

    __half* gh;
    float*  gagg;
    cudaGetSymbolAddress((void**)&gh, g_h16);
    cudaGetSymbolAddress((void**)&gagg, g_agg);

    // CSR build (amortized over both layers)
    k_detect_zero<<<(NN + 255) / 256, 256>>>((const int*)edges, (const int*)uidx, (const int*)jidx);
    k_count<<<EE / 256, 256>>>(edges);
    k_scanA<<<NBLK_SCAN, 1024>>>();
    k_scanB<<<1, 256>>>();
    k_scanC<<<(NN + 255) / 256, 256>>>();
    k_fill<<<EE / 256, 256>>>(edges);

    // ---- layer 1 ----
    k_gemm<<<(NN + GR - 1) / GR, 256>>>(user_emb, job_emb, nullptr, 0, W1, gh);
    k_gather<<<(NN * 32 + 255) / 256, 256>>>(gh, gagg);

    // ---- layer 2 (h only; aggregation fused into predictor at sampled nodes) ----
    k_gemm<<<(NN + GR - 1) / GR, 256>>>(gagg, nullptr, b1, 1, W2, gh);

    // ---- fused gather + predictor ----
    k_gpred<<<(BB * 32 + 255) / 256, 256>>>(uidx, jidx, gh, b2, pw, pb, out);
}